// round 12
// baseline (speedup 1.0000x reference)
#include <cuda_runtime.h>
#include <cuda_fp16.h>
#include <math.h>
#include <cstdint>

#define CDIM 128
#define BDIM 8
#define NDIM 2048

// ------- GEMM tiling: CTA m32 x n128, BK=64, double buffer, 3 CTAs/SM -------
#define BK 64
#define NITER (NDIM / BK)            // 32
#define A_ROWF 72                    // fp32 floats per A row (64 data + 8 pad)
#define A_STF  (32 * A_ROWF)         // 2304 floats per A stage
#define A_STB  (A_STF * 4)           // 9216 B
#define B_ROWP 72                    // halves per B row (64 data + 8 pad)
#define B_STB  (136 * B_ROWP * 2)    // 19584 B (128 g + 1 w + 7 zero)
#define B_OFFB (2 * A_STB)           // 18432
#define DEN_OFFB (B_OFFB + 2 * B_STB)  // 57600
#define SMEM_TOTAL (DEN_OFFB + 32 * 4) // 57728 B  -> 3 CTAs/SM

// ---------------- device scratch ----------------
__device__ __half g_gT[BDIM * CDIM * NDIM];  // [b][c][j] = fp16(w*h)
__device__ __half g_w[BDIM * NDIM];          // [b][j]    = fp16(w)

// ---------------- helpers ----------------
__device__ __forceinline__ uint32_t smem_u32(const void* p) {
    uint32_t a;
    asm("{ .reg .u64 t; cvta.to.shared.u64 t, %1; cvt.u32.u64 %0, t; }" : "=r"(a) : "l"(p));
    return a;
}
__device__ __forceinline__ void cp16(uint32_t dst, const void* src) {
    asm volatile("cp.async.cg.shared.global [%0], [%1], 16;" :: "r"(dst), "l"(src));
}
#define CP_COMMIT() asm volatile("cp.async.commit_group;" ::: "memory")
#define CP_WAIT0()  asm volatile("cp.async.wait_group 0;" ::: "memory")

#define LDSM_X4(r0, r1, r2, r3, a) \
    asm volatile("ldmatrix.sync.aligned.m8n8.x4.shared.b16 {%0,%1,%2,%3}, [%4];" \
        : "=r"(r0), "=r"(r1), "=r"(r2), "=r"(r3) : "r"(a))
#define LDSM_X2(r0, r1, a) \
    asm volatile("ldmatrix.sync.aligned.m8n8.x2.shared.b16 {%0,%1}, [%2];" \
        : "=r"(r0), "=r"(r1) : "r"(a))

#define MMA_F16(d, a0, a1, a2, a3, b0, b1) \
    asm volatile("mma.sync.aligned.m16n8k16.row.col.f32.f16.f16.f32 " \
        "{%0,%1,%2,%3}, {%4,%5,%6,%7}, {%8,%9}, {%0,%1,%2,%3};" \
        : "+f"((d)[0]), "+f"((d)[1]), "+f"((d)[2]), "+f"((d)[3]) \
        : "r"(a0), "r"(a1), "r"(a2), "r"(a3), "r"(b0), "r"(b1))

// ---------------------------------------------------------------------------
// prep_g (unchanged from R11): per 64-token tile, grid (32, 8), 256 thr.
// ---------------------------------------------------------------------------
#define PTOK 64
__global__ void __launch_bounds__(256)
prep_g_kernel(const float* __restrict__ h,
              const float* __restrict__ Ww,
              const float* __restrict__ Wb,
              const float* __restrict__ aw) {
    extern __shared__ float hs[];          // [64][129]
    __shared__ float vpart[8][128];
    __shared__ float spart[4][PTOK];
    __shared__ float awsh[CDIM];
    __shared__ float vsh[CDIM];
    __shared__ float wsh[PTOK];
    __shared__ float s0sh;

    const int b  = blockIdx.y;
    const int j0 = blockIdx.x * PTOK;
    const int tid = threadIdx.x;
    const int wid = tid >> 5, lid = tid & 31;

    if (tid < CDIM) awsh[tid] = aw[CDIM + tid];
    __syncthreads();

    {
        const int dp = wid, c4 = lid * 4;
        float4 acc4 = make_float4(0.f, 0.f, 0.f, 0.f);
#pragma unroll
        for (int q = 0; q < 16; q++) {
            int d = dp + q * 8;
            float a2 = awsh[d];
            float4 wv = *(const float4*)&Ww[(size_t)d * CDIM + c4];
            acc4.x = fmaf(wv.x, a2, acc4.x);
            acc4.y = fmaf(wv.y, a2, acc4.y);
            acc4.z = fmaf(wv.z, a2, acc4.z);
            acc4.w = fmaf(wv.w, a2, acc4.w);
        }
        *(float4*)&vpart[dp][c4] = acc4;
    }

    const float* hb = h + ((size_t)b * NDIM + j0) * CDIM;
#pragma unroll
    for (int l = 0; l < 8; l++) {
        int idx = tid + l * 256;
        int r = idx >> 5, c = (idx & 31) * 4;
        float4 v = *(const float4*)&hb[(size_t)r * CDIM + c];
        float* d = &hs[r * 129 + c];
        d[0] = v.x; d[1] = v.y; d[2] = v.z; d[3] = v.w;
    }
    __syncthreads();

    if (tid < CDIM) {
        float s = 0.f;
#pragma unroll
        for (int dp = 0; dp < 8; dp++) s += vpart[dp][tid];
        vsh[tid] = s;
    } else if (wid == 7) {
        float x = 0.f;
#pragma unroll
        for (int q = 0; q < 4; q++) {
            int d = lid + 32 * q;
            x += Wb[d] * awsh[d];
        }
#pragma unroll
        for (int o = 16; o > 0; o >>= 1) x += __shfl_down_sync(0xffffffffu, x, o);
        if (lid == 0) s0sh = x;
    }
    __syncthreads();

    {
        const int part = tid >> 6, j = tid & 63;
        const int c0 = part * 32;
        float p = 0.f;
#pragma unroll
        for (int q = 0; q < 32; q++)
            p = fmaf(hs[j * 129 + c0 + q], vsh[c0 + q], p);
        spart[part][j] = p;
    }
    __syncthreads();
    if (tid < PTOK)
        wsh[tid] = expf(spart[0][tid] + spart[1][tid] + spart[2][tid] +
                        spart[3][tid] + s0sh);
    __syncthreads();

    __half* Gb = g_gT + (size_t)b * CDIM * NDIM;
#pragma unroll
    for (int l = 0; l < 32; l++) {
        int idx = tid + l * 256;
        int c = idx >> 6, j = idx & 63;
        Gb[(size_t)c * NDIM + j0 + j] = __float2half_rn(wsh[j] * hs[j * 129 + c]);
    }
    if (tid < PTOK) g_w[(size_t)b * NDIM + j0 + tid] = __float2half_rn(wsh[tid]);
}

// ---------------------------------------------------------------------------
// GEMM: Num[32x128] = A_tile . G^T (fp16 MMA), Den via w-row MMA.
// 256 thr = 8 warps (wm 0-1 x wn 0-3), warp tile m16 x n32.
// A cp.async'd as fp32 (stride 72 floats); fragments built via LDS.64 + cvt.
// B cp.async'd as fp16, ldmatrix. 3 CTAs/SM.
// ---------------------------------------------------------------------------
__device__ __forceinline__ void cpA(uint32_t sb, int s, int it, int tid,
                                    const float* __restrict__ Ab) {
    const int k0 = it * BK;
    const uint32_t base = sb + s * A_STB;
#pragma unroll
    for (int l = 0; l < 2; l++) {
        int idx = tid + l * 256;           // 512 float4 per stage
        int r = idx >> 4, c = idx & 15;
        cp16(base + (r * A_ROWF + c * 4) * 4, Ab + (size_t)r * NDIM + k0 + c * 4);
    }
}
__device__ __forceinline__ void cpB(uint32_t sb, int s, int it, int tid,
                                    const __half* __restrict__ Gb,
                                    const __half* __restrict__ wb) {
    const int k0 = it * BK;
    const uint32_t base = sb + B_OFFB + s * B_STB;
#pragma unroll
    for (int l = 0; l < 4; l++) {
        int idx = tid + l * 256;           // rows 0-127: 1024 chunks
        int r = idx >> 3, c = (idx & 7) * 8;
        cp16(base + (r * B_ROWP + c) * 2, Gb + (size_t)r * NDIM + k0 + c);
    }
    if (tid < 8)                            // w row (row 128)
        cp16(base + (128 * B_ROWP + tid * 8) * 2, wb + k0 + tid * 8);
}

__global__ void __launch_bounds__(256, 3)
attn_mma_kernel(const float* __restrict__ A, float* __restrict__ out) {
    extern __shared__ __align__(16) char smem[];
    const uint32_t sb = smem_u32(smem);
    const int tid = threadIdx.x;
    const int lane = tid & 31;
    const int g = lane >> 2, t = lane & 3;
    const int wid = tid >> 5;
    const int wm = wid >> 2, wn = wid & 3;
    const int b = blockIdx.y, m0 = blockIdx.x * 32;

    const float* __restrict__ Ab = A + (size_t)b * NDIM * NDIM + (size_t)m0 * NDIM;
    const __half* __restrict__ Gb = g_gT + (size_t)b * CDIM * NDIM;
    const __half* __restrict__ wb = g_w + (size_t)b * NDIM;

    // zero B pad rows (129..135) of both stages
#pragma unroll
    for (int s = 0; s < 2; s++)
        for (int i = tid; i < 7 * B_ROWP / 2; i += 256)
            *(uint32_t*)(smem + B_OFFB + s * B_STB + 129 * B_ROWP * 2 + i * 4) = 0u;

    float acc[4][4];                       // [ch][quad]
#pragma unroll
    for (int ch = 0; ch < 4; ch++)
#pragma unroll
        for (int q = 0; q < 4; q++) acc[ch][q] = 0.f;
    float dacc[4] = {0.f, 0.f, 0.f, 0.f};

    // A fragment LDS base (float2 units): row R = wm*16 + g, col 2t
    const int R = wm * 16 + g;
    const int aF2 = R * (A_ROWF / 2) + t;          // + kk*8 (+4 for k-hi) (+8*36 row+8)
    // B ldmatrix lane address (bytes, stage-relative)
    const uint32_t bLane = ((lane & 15) * B_ROWP + (lane >> 4) * 8) * 2;
    const int l16 = lane & 15;
    const uint32_t dLane = (((128 + (l16 & 7)) * B_ROWP) + (l16 >> 3) * 8) * 2;

    // prologue
    cpA(sb, 0, 0, tid, Ab);
    cpB(sb, 0, 0, tid, Gb, wb);
    CP_COMMIT();

    for (int it = 0; it < NITER; ++it) {
        const int s = it & 1;
        CP_WAIT0();
        __syncthreads();
        if (it + 1 < NITER) {
            cpA(sb, 1 - s, it + 1, tid, Ab);
            cpB(sb, 1 - s, it + 1, tid, Gb, wb);
        }
        CP_COMMIT();

        const float2* Af = (const float2*)(smem + s * A_STB);
        const uint32_t bBase = sb + B_OFFB + s * B_STB + (wn * 32 * B_ROWP) * 2 + bLane;
        const uint32_t dBase = sb + B_OFFB + s * B_STB + dLane;
#pragma unroll
        for (int kk = 0; kk < 4; kk++) {
            // ---- A fragment: 4 x LDS.64 + pack to half2 ----
            const int fi = aF2 + kk * 8;
            float2 p0 = Af[fi];
            float2 p1 = Af[fi + 8 * 36];
            float2 p2 = Af[fi + 4];
            float2 p3 = Af[fi + 8 * 36 + 4];
            __half2 h0 = __floats2half2_rn(p0.x, p0.y);
            __half2 h1 = __floats2half2_rn(p1.x, p1.y);
            __half2 h2 = __floats2half2_rn(p2.x, p2.y);
            __half2 h3 = __floats2half2_rn(p3.x, p3.y);
            uint32_t a0 = *(uint32_t*)&h0, a1 = *(uint32_t*)&h1;
            uint32_t a2 = *(uint32_t*)&h2, a3 = *(uint32_t*)&h3;

            // ---- B fragments ----
            const uint32_t kb = kk * 32;   // 16 halves = 32 B
            uint32_t b0[4], b1[4];
#pragma unroll
            for (int nh = 0; nh < 2; nh++) {
                uint32_t r0, r1, r2, r3;
                LDSM_X4(r0, r1, r2, r3, bBase + nh * 16 * B_ROWP * 2 + kb);
                b0[nh * 2]     = r0; b1[nh * 2]     = r2;
                b0[nh * 2 + 1] = r1; b1[nh * 2 + 1] = r3;
            }
#pragma unroll
            for (int ch = 0; ch < 4; ch++)
                MMA_F16(acc[ch], a0, a1, a2, a3, b0[ch], b1[ch]);
            if (wn == 0) {
                uint32_t w0, w1;
                LDSM_X2(w0, w1, dBase + kb);
                MMA_F16(dacc, a0, a1, a2, a3, w0, w1);
            }
        }
    }

    __syncthreads();

    // publish den (n=0 col of dacc: c0 -> row R, c2 -> row R+8, at t==0)
    float* denS = (float*)(smem + DEN_OFFB);
    if (wn == 0 && t == 0) {
        denS[R]     = dacc[0];
        denS[R + 8] = dacc[2];
    }
    __syncthreads();

    // scale + stage to smem stg[32][132]
    float* stg = (float*)smem;
    {
        const float inv0 = 1.0f / denS[R];
        const float inv1 = 1.0f / denS[R + 8];
#pragma unroll
        for (int ch = 0; ch < 4; ch++) {
            const int col = wn * 32 + ch * 8 + 2 * t;
            *(float2*)&stg[R * 132 + col] =
                make_float2(acc[ch][0] * inv0, acc[ch][1] * inv0);
            *(float2*)&stg[(R + 8) * 132 + col] =
                make_float2(acc[ch][2] * inv1, acc[ch][3] * inv1);
        }
    }
    __syncthreads();

    float* __restrict__ ob = out + ((size_t)b * NDIM + m0) * CDIM;
#pragma unroll
    for (int l = 0; l < 4; l++) {
        int idx = tid + l * 256;           // 1024 float4
        int r = idx >> 5, c = idx & 31;
        *(float4*)&ob[r * CDIM + c * 4] = *(const float4*)&stg[r * 132 + c * 4];
    }
}

// ---------------------------------------------------------------------------
extern "C" void kernel_launch(void* const* d_in, const int* in_sizes, int n_in,
                              void* d_out, int out_size) {
    (void)in_sizes; (void)n_in; (void)out_size;
    const float* h  = (const float*)d_in[0];
    const float* A  = (const float*)d_in[1];
    const float* Ww = (const float*)d_in[2];
    const float* Wb = (const float*)d_in[3];
    const float* aw = (const float*)d_in[4];
    float* out = (float*)d_out;

    cudaFuncSetAttribute(prep_g_kernel,
                         cudaFuncAttributeMaxDynamicSharedMemorySize, PTOK * 129 * 4);
    cudaFuncSetAttribute(attn_mma_kernel,
                         cudaFuncAttributeMaxDynamicSharedMemorySize, SMEM_TOTAL);

    prep_g_kernel<<<dim3(NDIM / PTOK, BDIM), 256, PTOK * 129 * 4>>>(h, Ww, Wb, aw);
    attn_mma_kernel<<<dim3(NDIM / 32, BDIM), 256, SMEM_TOTAL>>>(A, out);
}

// round 13
// speedup vs baseline: 1.5419x; 1.5419x over previous
#include <cuda_runtime.h>
#include <cuda_fp16.h>
#include <math.h>
#include <cstdint>

#define CDIM 128
#define BDIM 8
#define NDIM 2048

// ------- GEMM tiling: CTA m64 x n128, BK=64, 3-stage pipeline -------
#define NSTAGE 3
#define BK 64
#define NITER (NDIM / BK)          // 32
#define A_ROWP 72                  // halves per row (64 data + 8 pad) -> 144B stride
#define A_STB (64 * A_ROWP * 2)    // 9216 B per A stage
#define B_STB (136 * A_ROWP * 2)   // 19584 B per B stage (128 g + 1 w + 7 zero)
#define B_OFFB (NSTAGE * A_STB)    // 27648
#define DEN_OFFB (B_OFFB + NSTAGE * B_STB)   // 86400
#define SMEM_TOTAL (DEN_OFFB + 64 * 4)       // 86656 B -> 2 CTAs/SM

// ---------------- device scratch ----------------
__device__ __half g_gT[BDIM * CDIM * NDIM];  // [b][c][j] = fp16(w*h)
__device__ __half g_w[BDIM * NDIM];          // [b][j]    = fp16(w)

// ---------------- helpers ----------------
__device__ __forceinline__ uint32_t smem_u32(const void* p) {
    uint32_t a;
    asm("{ .reg .u64 t; cvta.to.shared.u64 t, %1; cvt.u32.u64 %0, t; }" : "=r"(a) : "l"(p));
    return a;
}
__device__ __forceinline__ void cp16(uint32_t dst, const void* src) {
    asm volatile("cp.async.cg.shared.global [%0], [%1], 16;" :: "r"(dst), "l"(src));
}
#define CP_COMMIT() asm volatile("cp.async.commit_group;" ::: "memory")
#define CP_WAIT1()  asm volatile("cp.async.wait_group 1;" ::: "memory")

#define LDSM_X4(r0, r1, r2, r3, a) \
    asm volatile("ldmatrix.sync.aligned.m8n8.x4.shared.b16 {%0,%1,%2,%3}, [%4];" \
        : "=r"(r0), "=r"(r1), "=r"(r2), "=r"(r3) : "r"(a))
#define LDSM_X2(r0, r1, a) \
    asm volatile("ldmatrix.sync.aligned.m8n8.x2.shared.b16 {%0,%1}, [%2];" \
        : "=r"(r0), "=r"(r1) : "r"(a))

#define MMA_F16(d, a0, a1, a2, a3, b0, b1) \
    asm volatile("mma.sync.aligned.m16n8k16.row.col.f32.f16.f16.f32 " \
        "{%0,%1,%2,%3}, {%4,%5,%6,%7}, {%8,%9}, {%0,%1,%2,%3};" \
        : "+f"((d)[0]), "+f"((d)[1]), "+f"((d)[2]), "+f"((d)[3]) \
        : "r"(a0), "r"(a1), "r"(a2), "r"(a3), "r"(b0), "r"(b1))

// ---------------------------------------------------------------------------
// prep_g (same as R11): per 64-token tile, grid (32, 8), 256 thr.
// ---------------------------------------------------------------------------
#define PTOK 64
__global__ void __launch_bounds__(256)
prep_g_kernel(const float* __restrict__ h,
              const float* __restrict__ Ww,
              const float* __restrict__ Wb,
              const float* __restrict__ aw) {
    extern __shared__ float hs[];          // [64][129]
    __shared__ float vpart[8][128];
    __shared__ float spart[4][PTOK];
    __shared__ float awsh[CDIM];
    __shared__ float vsh[CDIM];
    __shared__ float wsh[PTOK];
    __shared__ float s0sh;

    const int b  = blockIdx.y;
    const int j0 = blockIdx.x * PTOK;
    const int tid = threadIdx.x;
    const int wid = tid >> 5, lid = tid & 31;

    if (tid < CDIM) awsh[tid] = aw[CDIM + tid];
    __syncthreads();

    {
        const int dp = wid, c4 = lid * 4;
        float4 acc4 = make_float4(0.f, 0.f, 0.f, 0.f);
#pragma unroll
        for (int q = 0; q < 16; q++) {
            int d = dp + q * 8;
            float a2 = awsh[d];
            float4 wv = *(const float4*)&Ww[(size_t)d * CDIM + c4];
            acc4.x = fmaf(wv.x, a2, acc4.x);
            acc4.y = fmaf(wv.y, a2, acc4.y);
            acc4.z = fmaf(wv.z, a2, acc4.z);
            acc4.w = fmaf(wv.w, a2, acc4.w);
        }
        *(float4*)&vpart[dp][c4] = acc4;
    }

    const float* hb = h + ((size_t)b * NDIM + j0) * CDIM;
#pragma unroll
    for (int l = 0; l < 8; l++) {
        int idx = tid + l * 256;
        int r = idx >> 5, c = (idx & 31) * 4;
        float4 v = *(const float4*)&hb[(size_t)r * CDIM + c];
        float* d = &hs[r * 129 + c];
        d[0] = v.x; d[1] = v.y; d[2] = v.z; d[3] = v.w;
    }
    __syncthreads();

    if (tid < CDIM) {
        float s = 0.f;
#pragma unroll
        for (int dp = 0; dp < 8; dp++) s += vpart[dp][tid];
        vsh[tid] = s;
    } else if (wid == 7) {
        float x = 0.f;
#pragma unroll
        for (int q = 0; q < 4; q++) {
            int d = lid + 32 * q;
            x += Wb[d] * awsh[d];
        }
#pragma unroll
        for (int o = 16; o > 0; o >>= 1) x += __shfl_down_sync(0xffffffffu, x, o);
        if (lid == 0) s0sh = x;
    }
    __syncthreads();

    {
        const int part = tid >> 6, j = tid & 63;
        const int c0 = part * 32;
        float p = 0.f;
#pragma unroll
        for (int q = 0; q < 32; q++)
            p = fmaf(hs[j * 129 + c0 + q], vsh[c0 + q], p);
        spart[part][j] = p;
    }
    __syncthreads();
    if (tid < PTOK)
        wsh[tid] = expf(spart[0][tid] + spart[1][tid] + spart[2][tid] +
                        spart[3][tid] + s0sh);
    __syncthreads();

    __half* Gb = g_gT + (size_t)b * CDIM * NDIM;
#pragma unroll
    for (int l = 0; l < 32; l++) {
        int idx = tid + l * 256;
        int c = idx >> 6, j = idx & 63;
        Gb[(size_t)c * NDIM + j0 + j] = __float2half_rn(wsh[j] * hs[j * 129 + c]);
    }
    if (tid < PTOK) g_w[(size_t)b * NDIM + j0 + tid] = __float2half_rn(wsh[tid]);
}

// ---------------------------------------------------------------------------
// Main GEMM (fp16 mma.sync): Num[64x128] = A_tile . G^T, Den via w-row MMA.
// 256 thr = 8 warps (wm 0-1 x wn 0-3), warp tile m32 x n32.
// BK=64, 3-stage: one cp.async group stays in flight during compute.
// ---------------------------------------------------------------------------
__device__ __forceinline__ void ldgA(const float* __restrict__ Ab, int it, int tid,
                                     float4 (&ra)[4]) {
    const float* src = Ab + it * BK;
#pragma unroll
    for (int l = 0; l < 4; l++) {
        int idx = tid + l * 256;           // 1024 float4 per stage
        int r = idx >> 4, c = (idx & 15) * 4;
        ra[l] = *(const float4*)&src[(size_t)r * NDIM + c];
    }
}
__device__ __forceinline__ void stsA(uint32_t sb, int s, int tid, const float4 (&ra)[4]) {
    const uint32_t base = sb + s * A_STB;
#pragma unroll
    for (int l = 0; l < 4; l++) {
        int idx = tid + l * 256;
        int r = idx >> 4, c = (idx & 15) * 4;
        __half2 h0 = __floats2half2_rn(ra[l].x, ra[l].y);
        __half2 h1 = __floats2half2_rn(ra[l].z, ra[l].w);
        asm volatile("st.shared.v2.b32 [%0], {%1,%2};"
                     :: "r"(base + (r * A_ROWP + c) * 2),
                        "r"(*(uint32_t*)&h0), "r"(*(uint32_t*)&h1) : "memory");
    }
}
__device__ __forceinline__ void cpB(uint32_t sb, int s, int it, int tid,
                                    const __half* __restrict__ Gb,
                                    const __half* __restrict__ wb) {
    const int k0 = it * BK;
    const uint32_t base = sb + B_OFFB + s * B_STB;
#pragma unroll
    for (int l = 0; l < 4; l++) {
        int idx = tid + l * 256;           // rows 0-127: 1024 chunks
        int r = idx >> 3, c = (idx & 7) * 8;
        cp16(base + (r * A_ROWP + c) * 2, Gb + (size_t)r * NDIM + k0 + c);
    }
    if (tid < 8)                            // w row (row 128): 8 chunks
        cp16(base + (128 * A_ROWP + tid * 8) * 2, wb + k0 + tid * 8);
}

__global__ void __launch_bounds__(256, 2)
attn_mma_kernel(const float* __restrict__ A, float* __restrict__ out) {
    extern __shared__ __align__(16) char smem[];
    const uint32_t sb = smem_u32(smem);
    const int tid = threadIdx.x;
    const int lane = tid & 31;
    const int g = lane >> 2, t = lane & 3;
    const int wid = tid >> 5;
    const int wm = wid >> 2, wn = wid & 3;
    const int b = blockIdx.y, m0 = blockIdx.x * 64;

    const float* __restrict__ Ab = A + (size_t)b * NDIM * NDIM + (size_t)m0 * NDIM;
    const __half* __restrict__ Gb = g_gT + (size_t)b * CDIM * NDIM;
    const __half* __restrict__ wb = g_w + (size_t)b * NDIM;

    // zero B pad rows (129..135) of all stages
#pragma unroll
    for (int s = 0; s < NSTAGE; s++)
        for (int i = tid; i < 7 * A_ROWP / 2; i += 256)
            *(uint32_t*)(smem + B_OFFB + s * B_STB + 129 * A_ROWP * 2 + i * 4) = 0u;

    float acc[2][4][4];
#pragma unroll
    for (int mf = 0; mf < 2; mf++)
#pragma unroll
        for (int ch = 0; ch < 4; ch++)
#pragma unroll
            for (int q = 0; q < 4; q++) acc[mf][ch][q] = 0.f;
    float dacc[2][4];
#pragma unroll
    for (int mf = 0; mf < 2; mf++)
#pragma unroll
        for (int q = 0; q < 4; q++) dacc[mf][q] = 0.f;

    // ldmatrix lane addresses (stage-relative, bytes)
    const uint32_t aLane = ((lane & 15) * A_ROWP + (lane >> 4) * 8) * 2;
    const uint32_t bLane = aLane;
    const int l16 = lane & 15;
    const uint32_t dLane = (((128 + (l16 & 7)) * A_ROWP) + (l16 >> 3) * 8) * 2;

    // prologue: stages 0,1 staged; A for stage 2 in regs
    float4 ra[4];
    ldgA(Ab, 0, tid, ra);
    stsA(sb, 0, tid, ra);
    cpB(sb, 0, 0, tid, Gb, wb); CP_COMMIT();
    ldgA(Ab, 1, tid, ra);
    stsA(sb, 1, tid, ra);
    cpB(sb, 1, 1, tid, Gb, wb); CP_COMMIT();
    ldgA(Ab, 2, tid, ra);

    int s = 0;
    for (int it = 0; it < NITER; ++it) {
        CP_WAIT1();                 // stage s B resident (one group may remain in flight)
        __syncthreads();            // compute of it-1 done -> stage (it+2)%3 free

        const int ns = (s + 2 >= NSTAGE) ? s + 2 - NSTAGE : s + 2;
        if (it + 2 < NITER) {
            stsA(sb, ns, tid, ra);                    // A for it+2
            cpB(sb, ns, it + 2, tid, Gb, wb);         // B for it+2
        }
        CP_COMMIT();
        if (it + 3 < NITER) ldgA(Ab, it + 3, tid, ra);

        const uint32_t aBase = sb + s * A_STB + (wm * 32 * A_ROWP) * 2 + aLane;
        const uint32_t bBase = sb + B_OFFB + s * B_STB + (wn * 32 * A_ROWP) * 2 + bLane;
        const uint32_t dBase = sb + B_OFFB + s * B_STB + dLane;
#pragma unroll
        for (int kk = 0; kk < 4; kk++) {
            const uint32_t kb = kk * 32;   // 16 halves = 32 B
            uint32_t a0[2], a1[2], a2[2], a3[2];
#pragma unroll
            for (int mf = 0; mf < 2; mf++)
                LDSM_X4(a0[mf], a1[mf], a2[mf], a3[mf],
                        aBase + mf * 16 * A_ROWP * 2 + kb);
            uint32_t b0[4], b1[4];
#pragma unroll
            for (int nh = 0; nh < 2; nh++) {
                uint32_t r0, r1, r2, r3;
                LDSM_X4(r0, r1, r2, r3, bBase + nh * 16 * A_ROWP * 2 + kb);
                b0[nh * 2]     = r0; b1[nh * 2]     = r2;
                b0[nh * 2 + 1] = r1; b1[nh * 2 + 1] = r3;
            }
#pragma unroll
            for (int mf = 0; mf < 2; mf++)
#pragma unroll
                for (int ch = 0; ch < 4; ch++)
                    MMA_F16(acc[mf][ch], a0[mf], a1[mf], a2[mf], a3[mf],
                            b0[ch], b1[ch]);
            if (wn == 0) {
                uint32_t w0, w1;
                LDSM_X2(w0, w1, dBase + kb);
#pragma unroll
                for (int mf = 0; mf < 2; mf++)
                    MMA_F16(dacc[mf], a0[mf], a1[mf], a2[mf], a3[mf], w0, w1);
            }
        }
        s = (s + 1 >= NSTAGE) ? 0 : s + 1;
    }

    __syncthreads();

    // publish den (n=0 column of dacc: c0 -> row g, c2 -> row g+8, at t==0)
    float* denS = (float*)(smem + DEN_OFFB);
    if (wn == 0 && t == 0) {
#pragma unroll
        for (int mf = 0; mf < 2; mf++) {
            denS[wm * 32 + mf * 16 + g]     = dacc[mf][0];
            denS[wm * 32 + mf * 16 + g + 8] = dacc[mf][2];
        }
    }
    __syncthreads();

    // scale + stage to smem stg[64][132]
    float* stg = (float*)smem;
#pragma unroll
    for (int mf = 0; mf < 2; mf++) {
        const int r0 = wm * 32 + mf * 16 + g;
        const int r1 = r0 + 8;
        const float inv0 = 1.0f / denS[r0];
        const float inv1 = 1.0f / denS[r1];
#pragma unroll
        for (int ch = 0; ch < 4; ch++) {
            const int col = wn * 32 + ch * 8 + 2 * t;
            *(float2*)&stg[r0 * 132 + col] =
                make_float2(acc[mf][ch][0] * inv0, acc[mf][ch][1] * inv0);
            *(float2*)&stg[r1 * 132 + col] =
                make_float2(acc[mf][ch][2] * inv1, acc[mf][ch][3] * inv1);
        }
    }
    __syncthreads();

    float* __restrict__ ob = out + ((size_t)b * NDIM + m0) * CDIM;
#pragma unroll
    for (int l = 0; l < 8; l++) {
        int idx = tid + l * 256;           // 2048 float4
        int r = idx >> 5, c = idx & 31;
        *(float4*)&ob[r * CDIM + c * 4] = *(const float4*)&stg[r * 132 + c * 4];
    }
}

// ---------------------------------------------------------------------------
extern "C" void kernel_launch(void* const* d_in, const int* in_sizes, int n_in,
                              void* d_out, int out_size) {
    (void)in_sizes; (void)n_in; (void)out_size;
    const float* h  = (const float*)d_in[0];
    const float* A  = (const float*)d_in[1];
    const float* Ww = (const float*)d_in[2];
    const float* Wb = (const float*)d_in[3];
    const float* aw = (const float*)d_in[4];
    float* out = (float*)d_out;

    cudaFuncSetAttribute(prep_g_kernel,
                         cudaFuncAttributeMaxDynamicSharedMemorySize, PTOK * 129 * 4);
    cudaFuncSetAttribute(attn_mma_kernel,
                         cudaFuncAttributeMaxDynamicSharedMemorySize, SMEM_TOTAL);

    prep_g_kernel<<<dim3(NDIM / PTOK, BDIM), 256, PTOK * 129 * 4>>>(h, Ww, Wb, aw);
    attn_mma_kernel<<<dim3(NDIM / 64, BDIM), 256, SMEM_TOTAL>>>(A, out);
}